// round 3
// baseline (speedup 1.0000x reference)
#include <cuda_runtime.h>
#include <math.h>

#define NP 100000
#define ND 20000
#define DD 128
#define EP 1600000
#define ED 800000
#define LN_EPS 1e-5f

// ---------------- scratch (static device globals; no runtime allocation) ----
__device__ float g_xw  [(size_t)NP * DD];  // x_prot @ W_gcn
__device__ float g_acc [(size_t)NP * DD];  // x3 + biases + 1e-6 + selfloop + ppi msgs
__device__ float g_dsum[(size_t)NP * DD];  // dti message sums
__device__ float g_yd  [(size_t)ND * DD];  // x_drug @ W_td + b_td
__device__ float g_deg [NP];
__device__ float g_dinv[NP];
__device__ float g_cnt [NP];

// ---------------- atomic helpers --------------------------------------------
// Native float4 atomicAdd (cc >= 9.0, CUDA >= 12.8). Result unused -> ptxas
// emits REDG.128 (no-return reduction). Scalar fallback for safety.
__device__ __forceinline__ void red_add_v4(float* p, float4 v) {
#if defined(__CUDA_ARCH__) && (__CUDA_ARCH__ >= 900)
    atomicAdd(reinterpret_cast<float4*>(p), v);
#else
    atomicAdd(p + 0, v.x);
    atomicAdd(p + 1, v.y);
    atomicAdd(p + 2, v.z);
    atomicAdd(p + 3, v.w);
#endif
}

// ---------------- init: zero dsum, deg=1 (self loop), cnt=0 -----------------
__global__ void k_init() {
    const int n4 = NP * DD / 4;
    const int stride = gridDim.x * blockDim.x;
    for (int i = blockIdx.x * blockDim.x + threadIdx.x; i < n4; i += stride) {
        reinterpret_cast<float4*>(g_dsum)[i] = make_float4(0.f, 0.f, 0.f, 0.f);
        if (i < NP) { g_deg[i] = 1.f; g_cnt[i] = 0.f; }
    }
}

// ---------------- degree accumulation over ppi col ---------------------------
__global__ void k_deg(const int* __restrict__ col) {
    const int stride = gridDim.x * blockDim.x;
#pragma unroll 4
    for (int e = blockIdx.x * blockDim.x + threadIdx.x; e < EP; e += stride)
        atomicAdd(&g_deg[__ldg(col + e)], 1.f);
}

__global__ void k_dinv() {
    int i = blockIdx.x * blockDim.x + threadIdx.x;
    if (i < NP) g_dinv[i] = rsqrtf(g_deg[i]);  // deg >= 1 always (self loop)
}

// ---------------- drug GEMM: g_yd = x_drug @ W_td + b_td --------------------
// Tile: 64 rows x 128 cols, 256 threads, micro-tile 8 rows x 4 cols.
__global__ __launch_bounds__(256) void k_gemm_drug(
    const float* __restrict__ x, const float* __restrict__ W,
    const float* __restrict__ b)
{
    extern __shared__ float sm[];
    float* sW  = sm;             // 128*128
    float* sXT = sm + DD * DD;   // 128 * 65 (k-major, padded)
    const int tid  = threadIdx.x;
    const int row0 = blockIdx.x * 64;

    for (int idx = tid; idx < DD * DD / 4; idx += 256)
        reinterpret_cast<float4*>(sW)[idx] =
            __ldg(reinterpret_cast<const float4*>(W) + idx);
    for (int idx = tid; idx < 64 * DD; idx += 256) {
        int r = idx >> 7, c = idx & 127;
        int gr = row0 + r;
        sXT[c * 65 + r] = (gr < ND) ? __ldg(x + (size_t)gr * DD + c) : 0.f;
    }
    __syncthreads();

    const int c0 = (tid & 31) * 4;
    const int r0 = (tid >> 5) * 8;
    float acc[8][4];
#pragma unroll
    for (int i = 0; i < 8; i++)
#pragma unroll
        for (int j = 0; j < 4; j++) acc[i][j] = 0.f;

#pragma unroll 4
    for (int k = 0; k < DD; k++) {
        float4 bb = *reinterpret_cast<const float4*>(sW + k * DD + c0);
        float a[8];
#pragma unroll
        for (int i = 0; i < 8; i++) a[i] = sXT[k * 65 + r0 + i];
#pragma unroll
        for (int i = 0; i < 8; i++) {
            acc[i][0] += a[i] * bb.x;
            acc[i][1] += a[i] * bb.y;
            acc[i][2] += a[i] * bb.z;
            acc[i][3] += a[i] * bb.w;
        }
    }

    float4 bias = __ldg(reinterpret_cast<const float4*>(b + c0));
#pragma unroll
    for (int i = 0; i < 8; i++) {
        int gr = row0 + r0 + i;
        if (gr < ND) {
            float4 o = make_float4(acc[i][0] + bias.x, acc[i][1] + bias.y,
                                   acc[i][2] + bias.z, acc[i][3] + bias.w);
            *reinterpret_cast<float4*>(g_yd + (size_t)gr * DD + c0) = o;
        }
    }
}

// ---------------- fused protein GEMMs ---------------------------------------
// g_xw  = x @ W_gcn
// g_acc = x @ W_pr + b_pr + b_gcn + 1e-6 + dinv[r]^2 * (x @ W_gcn)   (self loop)
__global__ __launch_bounds__(256) void k_gemm_prot(
    const float* __restrict__ x,
    const float* __restrict__ Wg, const float* __restrict__ Wp,
    const float* __restrict__ bg, const float* __restrict__ bp)
{
    extern __shared__ float sm[];
    float* sWg = sm;                 // 128*128
    float* sWp = sm + DD * DD;       // 128*128
    float* sXT = sm + 2 * DD * DD;   // 128 * 65
    const int tid  = threadIdx.x;
    const int row0 = blockIdx.x * 64;

    for (int idx = tid; idx < DD * DD / 4; idx += 256) {
        reinterpret_cast<float4*>(sWg)[idx] =
            __ldg(reinterpret_cast<const float4*>(Wg) + idx);
        reinterpret_cast<float4*>(sWp)[idx] =
            __ldg(reinterpret_cast<const float4*>(Wp) + idx);
    }
    for (int idx = tid; idx < 64 * DD; idx += 256) {
        int r = idx >> 7, c = idx & 127;
        int gr = row0 + r;
        sXT[c * 65 + r] = (gr < NP) ? __ldg(x + (size_t)gr * DD + c) : 0.f;
    }
    __syncthreads();

    const int c0 = (tid & 31) * 4;
    const int r0 = (tid >> 5) * 8;
    float accG[8][4], accP[8][4];
#pragma unroll
    for (int i = 0; i < 8; i++)
#pragma unroll
        for (int j = 0; j < 4; j++) { accG[i][j] = 0.f; accP[i][j] = 0.f; }

#pragma unroll 2
    for (int k = 0; k < DD; k++) {
        float4 bG = *reinterpret_cast<const float4*>(sWg + k * DD + c0);
        float4 bP = *reinterpret_cast<const float4*>(sWp + k * DD + c0);
        float a[8];
#pragma unroll
        for (int i = 0; i < 8; i++) a[i] = sXT[k * 65 + r0 + i];
#pragma unroll
        for (int i = 0; i < 8; i++) {
            accG[i][0] += a[i] * bG.x; accG[i][1] += a[i] * bG.y;
            accG[i][2] += a[i] * bG.z; accG[i][3] += a[i] * bG.w;
            accP[i][0] += a[i] * bP.x; accP[i][1] += a[i] * bP.y;
            accP[i][2] += a[i] * bP.z; accP[i][3] += a[i] * bP.w;
        }
    }

    float4 bg4 = __ldg(reinterpret_cast<const float4*>(bg + c0));
    float4 bp4 = __ldg(reinterpret_cast<const float4*>(bp + c0));
    float4 bias = make_float4(bg4.x + bp4.x + 1e-6f, bg4.y + bp4.y + 1e-6f,
                              bg4.z + bp4.z + 1e-6f, bg4.w + bp4.w + 1e-6f);
#pragma unroll
    for (int i = 0; i < 8; i++) {
        int gr = row0 + r0 + i;
        if (gr < NP) {
            float di = g_dinv[gr];
            float sl = di * di;
            float4 xg = make_float4(accG[i][0], accG[i][1], accG[i][2], accG[i][3]);
            *reinterpret_cast<float4*>(g_xw + (size_t)gr * DD + c0) = xg;
            float4 oa = make_float4(accP[i][0] + bias.x + sl * xg.x,
                                    accP[i][1] + bias.y + sl * xg.y,
                                    accP[i][2] + bias.z + sl * xg.z,
                                    accP[i][3] + bias.w + sl * xg.w);
            *reinterpret_cast<float4*>(g_acc + (size_t)gr * DD + c0) = oa;
        }
    }
}

// ---------------- PPI edge scatter: one warp per edge -----------------------
__global__ void k_ppi(const int* __restrict__ ei) {
    size_t t = (size_t)blockIdx.x * blockDim.x + threadIdx.x;
    int e = (int)(t >> 5);
    if (e >= EP) return;
    int lane = (int)(t & 31);
    int row = __ldg(ei + e);
    int col = __ldg(ei + EP + e);
    float nrm = g_dinv[row] * g_dinv[col];
    float4 v = *reinterpret_cast<const float4*>(g_xw + (size_t)row * DD + lane * 4);
    v.x *= nrm; v.y *= nrm; v.z *= nrm; v.w *= nrm;
    red_add_v4(g_acc + (size_t)col * DD + lane * 4, v);
}

// ---------------- DTI edge scatter: one warp per edge -----------------------
__global__ void k_dti(const int* __restrict__ dd, const int* __restrict__ dp) {
    size_t t = (size_t)blockIdx.x * blockDim.x + threadIdx.x;
    int e = (int)(t >> 5);
    if (e >= ED) return;
    int lane = (int)(t & 31);
    int drug = __ldg(dd + e);
    int prot = __ldg(dp + e);
    float4 v = *reinterpret_cast<const float4*>(g_yd + (size_t)drug * DD + lane * 4);
    red_add_v4(g_dsum + (size_t)prot * DD + lane * 4, v);
    if (lane == 0) atomicAdd(&g_cnt[prot], 1.f);
}

// ---------------- finalize: y = LN(acc + dsum/cnt), warp per row ------------
__global__ void k_fin(float* __restrict__ out) {
    size_t t = (size_t)blockIdx.x * blockDim.x + threadIdx.x;
    int r = (int)(t >> 5);
    if (r >= NP) return;
    int lane = (int)(t & 31);
    float rc = 1.f / fmaxf(g_cnt[r], 1.f);
    float4 a = *reinterpret_cast<const float4*>(g_acc  + (size_t)r * DD + lane * 4);
    float4 s = *reinterpret_cast<const float4*>(g_dsum + (size_t)r * DD + lane * 4);
    float4 v = make_float4(a.x + s.x * rc, a.y + s.y * rc,
                           a.z + s.z * rc, a.w + s.w * rc);
    float sum = v.x + v.y + v.z + v.w;
#pragma unroll
    for (int off = 16; off > 0; off >>= 1)
        sum += __shfl_xor_sync(0xFFFFFFFFu, sum, off);
    float mu = sum * (1.f / DD);
    float4 d = make_float4(v.x - mu, v.y - mu, v.z - mu, v.w - mu);
    float ss = d.x * d.x + d.y * d.y + d.z * d.z + d.w * d.w;
#pragma unroll
    for (int off = 16; off > 0; off >>= 1)
        ss += __shfl_xor_sync(0xFFFFFFFFu, ss, off);
    float inv = rsqrtf(ss * (1.f / DD) + LN_EPS);
    float4 o = make_float4(d.x * inv, d.y * inv, d.z * inv, d.w * inv);
    *reinterpret_cast<float4*>(out + (size_t)r * DD + lane * 4) = o;
}

// ---------------- launch ----------------------------------------------------
extern "C" void kernel_launch(void* const* d_in, const int* in_sizes, int n_in,
                              void* d_out, int out_size) {
    const float* x_prot = (const float*)d_in[0];
    const float* x_drug = (const float*)d_in[1];
    const float* W_gcn  = (const float*)d_in[2];
    const float* b_gcn  = (const float*)d_in[3];
    const float* W_td   = (const float*)d_in[4];
    const float* b_td   = (const float*)d_in[5];
    const float* W_pr   = (const float*)d_in[6];
    const float* b_pr   = (const float*)d_in[7];
    const int*   ppi    = (const int*)d_in[8];   // [2, EP] flattened
    const int*   dti_d  = (const int*)d_in[9];
    const int*   dti_p  = (const int*)d_in[10];
    float* out = (float*)d_out;

    const int SMEM_DRUG = (DD * DD + DD * 65) * 4;      // 98816 B
    const int SMEM_PROT = (2 * DD * DD + DD * 65) * 4;  // 164352 B
    cudaFuncSetAttribute(k_gemm_drug, cudaFuncAttributeMaxDynamicSharedMemorySize, SMEM_DRUG);
    cudaFuncSetAttribute(k_gemm_prot, cudaFuncAttributeMaxDynamicSharedMemorySize, SMEM_PROT);

    // 1. init (dsum zero, deg=1, cnt=0)
    k_init<<<(NP * DD / 4 + 255) / 256, 256>>>();
    // 2. degree
    k_deg<<<1184, 256>>>(ppi + EP);   // ~2 waves of 148 SMs, grid-stride
    // 3. dinv
    k_dinv<<<(NP + 255) / 256, 256>>>();
    // 4. drug GEMM (independent)
    k_gemm_drug<<<(ND + 63) / 64, 256, SMEM_DRUG>>>(x_drug, W_td, b_td);
    // 5. fused protein GEMMs (needs dinv for self-loop term)
    k_gemm_prot<<<(NP + 63) / 64, 256, SMEM_PROT>>>(x_prot, W_gcn, W_pr, b_gcn, b_pr);
    // 6. PPI scatter (warp per edge)
    k_ppi<<<(int)(((size_t)EP * 32 + 255) / 256), 256>>>(ppi);
    // 7. DTI scatter (warp per edge)
    k_dti<<<(int)(((size_t)ED * 32 + 255) / 256), 256>>>(dti_d, dti_p);
    // 8. finalize + layernorm
    k_fin<<<(int)(((size_t)NP * 32 + 255) / 256), 256>>>(out);
}

// round 5
// speedup vs baseline: 1.0098x; 1.0098x over previous
#include <cuda_runtime.h>
#include <math.h>

#define NP 100000
#define ND 20000
#define DD 128
#define EP 1600000
#define ED 800000
#define LN_EPS 1e-5f
#define XPAD 132   // sX row stride: multiple of 4 (16B-aligned float4 rows), 4-bank skew

// ---------------- scratch (static device globals; no runtime allocation) ----
__device__ float g_xw  [(size_t)NP * DD];  // x_prot @ W_gcn
__device__ float g_acc [(size_t)NP * DD];  // everything accumulates here
__device__ float g_yd  [(size_t)ND * DD];  // x_drug @ W_td + b_td
__device__ float g_deg [NP];
__device__ float g_dinv[NP];
__device__ float g_cnt [NP];
__device__ float g_rcnt[NP];

// ---------------- f32x2 packed math -----------------------------------------
__device__ __forceinline__ void fma2(unsigned long long& d, unsigned long long a,
                                     unsigned long long b) {
    asm("fma.rn.f32x2 %0, %1, %2, %0;" : "+l"(d) : "l"(a), "l"(b));
}
__device__ __forceinline__ unsigned long long splat2(float x) {
    unsigned long long r;
    asm("mov.b64 %0, {%1, %1};" : "=l"(r) : "r"(__float_as_uint(x)));
    return r;
}
__device__ __forceinline__ float2 unpack2(unsigned long long v) {
    float2 f;
    asm("mov.b64 {%0, %1}, %2;" : "=f"(f.x), "=f"(f.y) : "l"(v));
    return f;
}

// ---------------- atomic helper ---------------------------------------------
__device__ __forceinline__ void red_add_v4(float* p, float4 v) {
#if defined(__CUDA_ARCH__) && (__CUDA_ARCH__ >= 900)
    atomicAdd(reinterpret_cast<float4*>(p), v);
#else
    atomicAdd(p + 0, v.x); atomicAdd(p + 1, v.y);
    atomicAdd(p + 2, v.z); atomicAdd(p + 3, v.w);
#endif
}

// ---------------- init: deg=1 (self loop), cnt=0 ----------------------------
__global__ void k_init() {
    int i = blockIdx.x * blockDim.x + threadIdx.x;
    if (i < NP) { g_deg[i] = 1.f; g_cnt[i] = 0.f; }
}

// ---------------- degree + dti count (fused, grid-stride) -------------------
__global__ void k_deg(const int* __restrict__ col, const int* __restrict__ dp) {
    const int stride = gridDim.x * blockDim.x;
    for (int e = blockIdx.x * blockDim.x + threadIdx.x; e < EP + ED; e += stride) {
        if (e < EP) atomicAdd(&g_deg[__ldg(col + e)], 1.f);
        else        atomicAdd(&g_cnt[__ldg(dp + (e - EP))], 1.f);
    }
}

__global__ void k_dinv() {
    int i = blockIdx.x * blockDim.x + threadIdx.x;
    if (i < NP) {
        g_dinv[i] = rsqrtf(g_deg[i]);            // deg >= 1 always
        g_rcnt[i] = 1.f / fmaxf(g_cnt[i], 1.f);
    }
}

// ---------------- fused protein GEMMs (FFMA2, 128x128 tile, 8x8 micro) ------
// g_xw  = x @ W_gcn
// g_acc = x @ W_pr + b_pr + b_gcn + 1e-6 + dinv[r]^2 * (x @ W_gcn)
__global__ __launch_bounds__(256, 1) void k_gemm_prot(
    const float* __restrict__ x,
    const float* __restrict__ Wg, const float* __restrict__ Wp,
    const float* __restrict__ bg, const float* __restrict__ bp)
{
    extern __shared__ float sm[];
    float* sWg = sm;                     // 128*128
    float* sWp = sm + DD * DD;           // 128*128
    float* sX  = sm + 2 * DD * DD;       // 128 * XPAD (k-major, padded)
    const int tid  = threadIdx.x;
    const int row0 = blockIdx.x * 128;

    for (int idx = tid; idx < DD * DD / 4; idx += 256) {
        reinterpret_cast<float4*>(sWg)[idx] = __ldg(reinterpret_cast<const float4*>(Wg) + idx);
        reinterpret_cast<float4*>(sWp)[idx] = __ldg(reinterpret_cast<const float4*>(Wp) + idx);
    }
    for (int idx = tid; idx < 128 * DD; idx += 256) {
        int r = idx >> 7, c = idx & 127;
        int gr = row0 + r;
        sX[c * XPAD + r] = (gr < NP) ? __ldg(x + (size_t)gr * DD + c) : 0.f;
    }
    __syncthreads();

    const int c0 = (tid & 15) * 8;
    const int r0 = (tid >> 4) * 8;
    unsigned long long aG[8][4], aP[8][4];
#pragma unroll
    for (int i = 0; i < 8; i++)
#pragma unroll
        for (int j = 0; j < 4; j++) { aG[i][j] = 0ull; aP[i][j] = 0ull; }

#pragma unroll 4
    for (int k = 0; k < DD; k++) {
        float4 alo = *reinterpret_cast<const float4*>(sX + k * XPAD + r0);
        float4 ahi = *reinterpret_cast<const float4*>(sX + k * XPAD + r0 + 4);
        ulonglong2 bg0 = *reinterpret_cast<const ulonglong2*>(sWg + k * DD + c0);
        ulonglong2 bg1 = *reinterpret_cast<const ulonglong2*>(sWg + k * DD + c0 + 4);
        ulonglong2 bp0 = *reinterpret_cast<const ulonglong2*>(sWp + k * DD + c0);
        ulonglong2 bp1 = *reinterpret_cast<const ulonglong2*>(sWp + k * DD + c0 + 4);
        float ar[8] = {alo.x, alo.y, alo.z, alo.w, ahi.x, ahi.y, ahi.z, ahi.w};
#pragma unroll
        for (int i = 0; i < 8; i++) {
            unsigned long long a2 = splat2(ar[i]);
            fma2(aG[i][0], a2, bg0.x); fma2(aG[i][1], a2, bg0.y);
            fma2(aG[i][2], a2, bg1.x); fma2(aG[i][3], a2, bg1.y);
            fma2(aP[i][0], a2, bp0.x); fma2(aP[i][1], a2, bp0.y);
            fma2(aP[i][2], a2, bp1.x); fma2(aP[i][3], a2, bp1.y);
        }
    }

    float4 bgA = __ldg(reinterpret_cast<const float4*>(bg + c0));
    float4 bgB = __ldg(reinterpret_cast<const float4*>(bg + c0 + 4));
    float4 bpA = __ldg(reinterpret_cast<const float4*>(bp + c0));
    float4 bpB = __ldg(reinterpret_cast<const float4*>(bp + c0 + 4));
    float bias[8] = {bgA.x + bpA.x + 1e-6f, bgA.y + bpA.y + 1e-6f,
                     bgA.z + bpA.z + 1e-6f, bgA.w + bpA.w + 1e-6f,
                     bgB.x + bpB.x + 1e-6f, bgB.y + bpB.y + 1e-6f,
                     bgB.z + bpB.z + 1e-6f, bgB.w + bpB.w + 1e-6f};
#pragma unroll
    for (int i = 0; i < 8; i++) {
        int gr = row0 + r0 + i;
        if (gr < NP) {
            float di = g_dinv[gr];
            float sl = di * di;
            float xg[8], xp[8];
#pragma unroll
            for (int j = 0; j < 4; j++) {
                float2 fg = unpack2(aG[i][j]); xg[2*j] = fg.x; xg[2*j+1] = fg.y;
                float2 fp = unpack2(aP[i][j]); xp[2*j] = fp.x; xp[2*j+1] = fp.y;
            }
            float* pw = g_xw  + (size_t)gr * DD + c0;
            float* pa = g_acc + (size_t)gr * DD + c0;
            *reinterpret_cast<float4*>(pw)     = make_float4(xg[0], xg[1], xg[2], xg[3]);
            *reinterpret_cast<float4*>(pw + 4) = make_float4(xg[4], xg[5], xg[6], xg[7]);
            float oa[8];
#pragma unroll
            for (int j = 0; j < 8; j++) oa[j] = xp[j] + bias[j] + sl * xg[j];
            *reinterpret_cast<float4*>(pa)     = make_float4(oa[0], oa[1], oa[2], oa[3]);
            *reinterpret_cast<float4*>(pa + 4) = make_float4(oa[4], oa[5], oa[6], oa[7]);
        }
    }
}

// ---------------- drug GEMM: g_yd = x_drug @ W_td + b_td (FFMA2) ------------
__global__ __launch_bounds__(256, 1) void k_gemm_drug(
    const float* __restrict__ x, const float* __restrict__ W,
    const float* __restrict__ b)
{
    extern __shared__ float sm[];
    float* sW = sm;                  // 128*128
    float* sX = sm + DD * DD;        // 128*XPAD
    const int tid  = threadIdx.x;
    const int row0 = blockIdx.x * 128;

    for (int idx = tid; idx < DD * DD / 4; idx += 256)
        reinterpret_cast<float4*>(sW)[idx] = __ldg(reinterpret_cast<const float4*>(W) + idx);
    for (int idx = tid; idx < 128 * DD; idx += 256) {
        int r = idx >> 7, c = idx & 127;
        int gr = row0 + r;
        sX[c * XPAD + r] = (gr < ND) ? __ldg(x + (size_t)gr * DD + c) : 0.f;
    }
    __syncthreads();

    const int c0 = (tid & 15) * 8;
    const int r0 = (tid >> 4) * 8;
    unsigned long long acc[8][4];
#pragma unroll
    for (int i = 0; i < 8; i++)
#pragma unroll
        for (int j = 0; j < 4; j++) acc[i][j] = 0ull;

#pragma unroll 4
    for (int k = 0; k < DD; k++) {
        float4 alo = *reinterpret_cast<const float4*>(sX + k * XPAD + r0);
        float4 ahi = *reinterpret_cast<const float4*>(sX + k * XPAD + r0 + 4);
        ulonglong2 b0 = *reinterpret_cast<const ulonglong2*>(sW + k * DD + c0);
        ulonglong2 b1 = *reinterpret_cast<const ulonglong2*>(sW + k * DD + c0 + 4);
        float ar[8] = {alo.x, alo.y, alo.z, alo.w, ahi.x, ahi.y, ahi.z, ahi.w};
#pragma unroll
        for (int i = 0; i < 8; i++) {
            unsigned long long a2 = splat2(ar[i]);
            fma2(acc[i][0], a2, b0.x); fma2(acc[i][1], a2, b0.y);
            fma2(acc[i][2], a2, b1.x); fma2(acc[i][3], a2, b1.y);
        }
    }

    float4 bA = __ldg(reinterpret_cast<const float4*>(b + c0));
    float4 bB = __ldg(reinterpret_cast<const float4*>(b + c0 + 4));
    float bias[8] = {bA.x, bA.y, bA.z, bA.w, bB.x, bB.y, bB.z, bB.w};
#pragma unroll
    for (int i = 0; i < 8; i++) {
        int gr = row0 + r0 + i;
        if (gr < ND) {
            float o[8];
#pragma unroll
            for (int j = 0; j < 4; j++) {
                float2 f = unpack2(acc[i][j]);
                o[2*j] = f.x + bias[2*j]; o[2*j+1] = f.y + bias[2*j+1];
            }
            float* py = g_yd + (size_t)gr * DD + c0;
            *reinterpret_cast<float4*>(py)     = make_float4(o[0], o[1], o[2], o[3]);
            *reinterpret_cast<float4*>(py + 4) = make_float4(o[4], o[5], o[6], o[7]);
        }
    }
}

// ---------------- PPI edge scatter: one warp per edge -----------------------
__global__ void k_ppi(const int* __restrict__ ei) {
    size_t t = (size_t)blockIdx.x * blockDim.x + threadIdx.x;
    int e = (int)(t >> 5);
    if (e >= EP) return;
    int lane = (int)(t & 31);
    int row = __ldg(ei + e);
    int col = __ldg(ei + EP + e);
    float nrm = g_dinv[row] * g_dinv[col];
    float4 v = *reinterpret_cast<const float4*>(g_xw + (size_t)row * DD + lane * 4);
    v.x *= nrm; v.y *= nrm; v.z *= nrm; v.w *= nrm;
    red_add_v4(g_acc + (size_t)col * DD + lane * 4, v);
}

// ---------------- DTI edge scatter: pre-scaled by 1/cnt, into g_acc ---------
__global__ void k_dti(const int* __restrict__ dd, const int* __restrict__ dp) {
    size_t t = (size_t)blockIdx.x * blockDim.x + threadIdx.x;
    int e = (int)(t >> 5);
    if (e >= ED) return;
    int lane = (int)(t & 31);
    int drug = __ldg(dd + e);
    int prot = __ldg(dp + e);
    float rc = g_rcnt[prot];
    float4 v = *reinterpret_cast<const float4*>(g_yd + (size_t)drug * DD + lane * 4);
    v.x *= rc; v.y *= rc; v.z *= rc; v.w *= rc;
    red_add_v4(g_acc + (size_t)prot * DD + lane * 4, v);
}

// ---------------- finalize: y = LN(g_acc), warp per row ---------------------
__global__ void k_fin(float* __restrict__ out) {
    size_t t = (size_t)blockIdx.x * blockDim.x + threadIdx.x;
    int r = (int)(t >> 5);
    if (r >= NP) return;
    int lane = (int)(t & 31);
    float4 v = *reinterpret_cast<const float4*>(g_acc + (size_t)r * DD + lane * 4);
    float sum = v.x + v.y + v.z + v.w;
#pragma unroll
    for (int off = 16; off > 0; off >>= 1)
        sum += __shfl_xor_sync(0xFFFFFFFFu, sum, off);
    float mu = sum * (1.f / DD);
    float4 d = make_float4(v.x - mu, v.y - mu, v.z - mu, v.w - mu);
    float ss = d.x * d.x + d.y * d.y + d.z * d.z + d.w * d.w;
#pragma unroll
    for (int off = 16; off > 0; off >>= 1)
        ss += __shfl_xor_sync(0xFFFFFFFFu, ss, off);
    float inv = rsqrtf(ss * (1.f / DD) + LN_EPS);
    float4 o = make_float4(d.x * inv, d.y * inv, d.z * inv, d.w * inv);
    *reinterpret_cast<float4*>(out + (size_t)r * DD + lane * 4) = o;
}

// ---------------- launch ----------------------------------------------------
extern "C" void kernel_launch(void* const* d_in, const int* in_sizes, int n_in,
                              void* d_out, int out_size) {
    const float* x_prot = (const float*)d_in[0];
    const float* x_drug = (const float*)d_in[1];
    const float* W_gcn  = (const float*)d_in[2];
    const float* b_gcn  = (const float*)d_in[3];
    const float* W_td   = (const float*)d_in[4];
    const float* b_td   = (const float*)d_in[5];
    const float* W_pr   = (const float*)d_in[6];
    const float* b_pr   = (const float*)d_in[7];
    const int*   ppi    = (const int*)d_in[8];   // [2, EP] flattened
    const int*   dti_d  = (const int*)d_in[9];
    const int*   dti_p  = (const int*)d_in[10];
    float* out = (float*)d_out;

    const int SMEM_PROT = (2 * DD * DD + DD * XPAD) * 4;  // 198656 B
    const int SMEM_DRUG = (DD * DD + DD * XPAD) * 4;      // 133120 B
    cudaFuncSetAttribute(k_gemm_prot, cudaFuncAttributeMaxDynamicSharedMemorySize, SMEM_PROT);
    cudaFuncSetAttribute(k_gemm_drug, cudaFuncAttributeMaxDynamicSharedMemorySize, SMEM_DRUG);

    // 1. init (deg=1, cnt=0)
    k_init<<<(NP + 255) / 256, 256>>>();
    // 2. degree + dti counts (fused grid-stride)
    k_deg<<<1184, 256>>>(ppi + EP, dti_p);
    // 3. dinv + rcnt
    k_dinv<<<(NP + 255) / 256, 256>>>();
    // 4. fused protein GEMMs  (profiled slot)
    k_gemm_prot<<<(NP + 127) / 128, 256, SMEM_PROT>>>(x_prot, W_gcn, W_pr, b_gcn, b_pr);
    // 5. PPI scatter (warp per edge)
    k_ppi<<<(int)(((size_t)EP * 32 + 255) / 256), 256>>>(ppi);
    // 6. drug GEMM
    k_gemm_drug<<<(ND + 127) / 128, 256, SMEM_DRUG>>>(x_drug, W_td, b_td);
    // 7. DTI scatter (pre-scaled mean, into g_acc)
    k_dti<<<(int)(((size_t)ED * 32 + 255) / 256), 256>>>(dti_d, dti_p);
    // 8. finalize + layernorm
    k_fin<<<(int)(((size_t)NP * 32 + 255) / 256), 256>>>(out);
}